// round 16
// baseline (speedup 1.0000x reference)
#include <cuda_runtime.h>
#include <cuda_bf16.h>
#include <math.h>

// ---------------- scratch (no cudaMalloc allowed) ----------------
__device__ __align__(16) float g_h1[4096];     // after in_W0
__device__ __align__(16) float g_h2[4096];     // after in_W1
__device__ __align__(16) float g_params[2112]; // after in_W2
__device__ __align__(16) float g_cpg[64];      // cpg_out
__device__ __align__(16) float g_h3[2048];     // after out_W0
__device__ __align__(16) float g_h4[2048];     // after out_W1
__device__ unsigned g_done = 0;                // last-block counter (self-resetting)

// ---------------- PDL helpers ----------------
__device__ __forceinline__ void pdl_trigger() {
#if defined(__CUDA_ARCH__) && __CUDA_ARCH__ >= 900
    cudaTriggerProgrammaticLaunchCompletion();
#endif
}
__device__ __forceinline__ void pdl_sync() {
#if defined(__CUDA_ARCH__) && __CUDA_ARCH__ >= 900
    cudaGridDependencySynchronize();
#endif
}
__device__ __forceinline__ void l2_pf_line(const char* p) {
    asm volatile("prefetch.global.L2 [%0];" :: "l"(p));
}

// ---------------- reductions ----------------
__device__ __forceinline__ float warp_reduce(float v) {
#pragma unroll
    for (int o = 16; o; o >>= 1) v += __shfl_down_sync(0xffffffffu, v, o);
    return v;
}

// ---------------- accurate sin: fp32 Cody-Waite 3-term + quadrant ----------
// Immune to --use_fast_math (hand-rolled). DP fallback for |x|>32768 (unused
// in practice). qoff=1 gives cos.
__device__ __forceinline__ float trig_acc(float x, int qoff) {
    float q, r;
    if (__builtin_expect(fabsf(x) > 32768.0f, 0)) {
        double xd = (double)x;
        double qd = rint(xd * 0.63661977236758138);
        q = (float)qd;
        r = (float)fma(qd, -1.5707963267948966, xd);
    } else {
        q = rintf(x * 0.63661977236758138f);
        r = fmaf(q, -1.5703125f, x);
        r = fmaf(q, -4.837512969970703125e-4f, r);
        r = fmaf(q, -7.549789948768648e-8f, r);
    }
    int n = ((int)q + qoff) & 3;
    float r2 = r * r;
    float ps = fmaf(r2, fmaf(r2, -1.9515295891e-4f, 8.3321608736e-3f), -1.6666654611e-1f);
    float s  = fmaf(r * r2, ps, r);
    float pc = fmaf(r2, fmaf(r2, -1.388731625493765e-3f, 4.166664568298827e-2f),
                    -4.999999905424326e-1f);
    float c  = fmaf(r2, pc, 1.0f);
    float v  = (n & 1) ? c : s;
    return (n & 2) ? -v : v;
}
__device__ __forceinline__ float sin_acc(float x) { return trig_acc(x, 0); }
__device__ __forceinline__ float cos_acc(float x) { return trig_acc(x, 1); }

// ---------------- CPG RK4(3/8) device function (256 threads) ----------------
// i = tid&31 (oscillator), g = tid>>5 (8 groups x 4 coupling partners).
// ODE (reference slot permutation replicated exactly):
//   s0' = s1
//   s1' = ifr[i] + sum_j s0[i]*cw[i][j]*sin(s2[j]-s2[i]-pb[i][j])
//   s2' = 1000*(250*(ia[i]-s0[i]) - s1[i])
// Output: a = new[0:32], ph = new[32:64]; cpg_out = [a*cos(ph), a*sin(ph)]
__device__ void cpg_compute(const float* params, const float* state,
                            const float* t_ptr, float* out_state, float* cpg_out) {
    const int tid = threadIdx.x;  // 0..255
    const int i   = tid & 31;
    const int g   = tid >> 5;     // 0..7

    __shared__ float sh_ph[2][32];
    __shared__ float sh_part[8][32];

    float cwv[4], pbv[4];
#pragma unroll
    for (int k = 0; k < 4; k++) {
        cwv[k] = __ldcg(params + 64 + 32 * i + 4 * g + k);
        pbv[k] = __ldcg(params + 64 + 1024 + 32 * i + 4 * g + k);
    }
    const float ia  = __ldcg(params + i);
    const float ifr = __ldcg(params + 32 + i);
    const float h   = *t_ptr;
    const float s0 = state[i], s1 = state[32 + i], s2 = state[64 + i];

    int stage = 0;
    auto f = [&](float a0, float a1, float a2, float& d0, float& d1, float& d2) {
        int buf = stage & 1;
        if (g == 0) sh_ph[buf][i] = a2;
        __syncthreads();
        const float* ph = sh_ph[buf] + 4 * g;
        float acc0, acc1;
        acc0 = cwv[0] * sin_acc(ph[0] - a2 - pbv[0]);
        acc1 = cwv[1] * sin_acc(ph[1] - a2 - pbv[1]);
        acc0 = fmaf(cwv[2], sin_acc(ph[2] - a2 - pbv[2]), acc0);
        acc1 = fmaf(cwv[3], sin_acc(ph[3] - a2 - pbv[3]), acc1);
        sh_part[g][i] = acc0 + acc1;
        __syncthreads();
        float coup = ((sh_part[0][i] + sh_part[1][i]) + (sh_part[2][i] + sh_part[3][i]))
                   + ((sh_part[4][i] + sh_part[5][i]) + (sh_part[6][i] + sh_part[7][i]));
        d1 = fmaf(a0, coup, ifr);
        d0 = a1;
        d2 = 1000.0f * fmaf(250.0f, ia - a0, -a1);
        stage++;
    };

    float k10, k11, k12, k20, k21, k22, k30, k31, k32, k40, k41, k42;
    f(s0, s1, s2, k10, k11, k12);
    f(s0 + h * k10 / 3.0f, s1 + h * k11 / 3.0f, s2 + h * k12 / 3.0f, k20, k21, k22);
    f(s0 + h * (k20 - k10 / 3.0f), s1 + h * (k21 - k11 / 3.0f), s2 + h * (k22 - k12 / 3.0f),
      k30, k31, k32);
    f(s0 + h * (k10 - k20 + k30), s1 + h * (k11 - k21 + k31), s2 + h * (k12 - k22 + k32),
      k40, k41, k42);

    float n0 = s0 + h * 0.125f * (k10 + 3.0f * (k20 + k30) + k40);
    float n1 = s1 + h * 0.125f * (k11 + 3.0f * (k21 + k31) + k41);
    float n2 = s2 + h * 0.125f * (k12 + 3.0f * (k22 + k32) + k42);

    if (g == 0) {
        out_state[i]      = n0;
        out_state[32 + i] = n1;
        out_state[64 + i] = n2;
        // a = n0, ph = n1 (reference reads ph from slot [n:2n])
        cpg_out[i]      = n0 * cos_acc(n1);
        cpg_out[32 + i] = n0 * sin_acc(n1);
    }
}

// ---------------- GEMV kernels (4 rows/block, PDL, 128-thread blocks) ------
// Small blocks keep adjacent PDL kernels fully co-resident: the successor's
// blocks park in pdl_sync BEFORE the predecessor finishes (zero sched ramp).

// Layer 0: rows=4096, cols=2049. Scalar loads; 4 rows/block; 128 threads.
__global__ void __launch_bounds__(128)
gemv_in0(const float* __restrict__ W, const float* __restrict__ b,
         const float* __restrict__ x, const float* __restrict__ t,
         float* __restrict__ y) {
    int r0 = blockIdx.x * 4;
    {   // prefetch this block's slice: 4*2049*4B = 257 lines (cover 256)
        const char* wb = (const char*)(W + (size_t)r0 * 2049);
        l2_pf_line(wb + (unsigned)threadIdx.x * 128u);
        l2_pf_line(wb + ((unsigned)threadIdx.x + 128u) * 128u);
    }
    pdl_trigger();
    pdl_sync();

    const float* W0 = W + (size_t)r0 * 2049;
    const float* W1 = W0 + 2049;
    const float* W2 = W1 + 2049;
    const float* W3 = W2 + 2049;
    float s0 = 0.0f, s1 = 0.0f, s2 = 0.0f, s3 = 0.0f;
#pragma unroll
    for (int it = 0; it < 16; it++) {
        int j = threadIdx.x + it * 128;
        float xv = x[j];
        s0 = fmaf(__ldcs(W0 + j), xv, s0);
        s1 = fmaf(__ldcs(W1 + j), xv, s1);
        s2 = fmaf(__ldcs(W2 + j), xv, s2);
        s3 = fmaf(__ldcs(W3 + j), xv, s3);
    }
    if (threadIdx.x == 0) {
        float tv = *t;
        s0 = fmaf(__ldcs(W0 + 2048), tv, s0);
        s1 = fmaf(__ldcs(W1 + 2048), tv, s1);
        s2 = fmaf(__ldcs(W2 + 2048), tv, s2);
        s3 = fmaf(__ldcs(W3 + 2048), tv, s3);
    }
    __shared__ float sm[4][4];
    int lane = threadIdx.x & 31, w = threadIdx.x >> 5;
    s0 = warp_reduce(s0); s1 = warp_reduce(s1);
    s2 = warp_reduce(s2); s3 = warp_reduce(s3);
    if (lane == 0) { sm[0][w] = s0; sm[1][w] = s1; sm[2][w] = s2; sm[3][w] = s3; }
    __syncthreads();
    if (threadIdx.x < 16) {
        int rr = threadIdx.x >> 2, sl = threadIdx.x & 3;
        float v = sm[rr][sl];
        v += __shfl_down_sync(0x0000ffffu, v, 2);
        v += __shfl_down_sync(0x0000ffffu, v, 1);
        if (sl == 0) y[r0 + rr] = fmaxf(v + b[r0 + rr], 0.0f);
    }
}

// float4 GEMV, 4 rows per 128-thread block.
template<int COLS, bool RELU>
__global__ void __launch_bounds__(128)
gemv4s(const float* __restrict__ W, const float* __restrict__ b,
       const float* __restrict__ x, float* __restrict__ y) {
    constexpr int N4 = COLS / 4;
    constexpr int ITERS = N4 / 128;
    constexpr int PF_ITERS = (COLS * 16 / 128) / 128;  // lines / threads
    int r0 = blockIdx.x * 4;
    {
        const char* wb = (const char*)(W + (size_t)r0 * COLS);
#pragma unroll
        for (int l = 0; l < PF_ITERS; l++)
            l2_pf_line(wb + ((unsigned)threadIdx.x + l * 128u) * 128u);
    }
    pdl_trigger();
    pdl_sync();

    const float4* W0 = (const float4*)(W + (size_t)r0 * COLS);
    const float4* W1 = (const float4*)(W + (size_t)(r0 + 1) * COLS);
    const float4* W2 = (const float4*)(W + (size_t)(r0 + 2) * COLS);
    const float4* W3 = (const float4*)(W + (size_t)(r0 + 3) * COLS);
    const float4* x4 = (const float4*)x;
    float s0 = 0.0f, s1 = 0.0f, s2 = 0.0f, s3 = 0.0f;
#pragma unroll
    for (int it = 0; it < ITERS; it++) {
        int j = threadIdx.x + it * 128;
        float4 v  = x4[j];
        float4 w0 = __ldcs(W0 + j);
        float4 w1 = __ldcs(W1 + j);
        float4 w2 = __ldcs(W2 + j);
        float4 w3 = __ldcs(W3 + j);
        s0 += w0.x * v.x + w0.y * v.y + w0.z * v.z + w0.w * v.w;
        s1 += w1.x * v.x + w1.y * v.y + w1.z * v.z + w1.w * v.w;
        s2 += w2.x * v.x + w2.y * v.y + w2.z * v.z + w2.w * v.w;
        s3 += w3.x * v.x + w3.y * v.y + w3.z * v.z + w3.w * v.w;
    }
    __shared__ float sm[4][4];
    int lane = threadIdx.x & 31, w = threadIdx.x >> 5;
    s0 = warp_reduce(s0); s1 = warp_reduce(s1);
    s2 = warp_reduce(s2); s3 = warp_reduce(s3);
    if (lane == 0) { sm[0][w] = s0; sm[1][w] = s1; sm[2][w] = s2; sm[3][w] = s3; }
    __syncthreads();
    if (threadIdx.x < 16) {
        int rr = threadIdx.x >> 2, sl = threadIdx.x & 3;
        float v = sm[rr][sl];
        v += __shfl_down_sync(0x0000ffffu, v, 2);
        v += __shfl_down_sync(0x0000ffffu, v, 1);
        if (sl == 0) {
            float r = v + b[r0 + rr];
            y[r0 + rr] = RELU ? fmaxf(r, 0.0f) : r;
        }
    }
}

// Fused params layer: 256 threads (cpg needs them), 4 rows/block, PDL.
// The last-arriving block runs the CPG step inline; nobody waits.
__global__ void __launch_bounds__(256)
gemv4_fuse(const float* __restrict__ W, const float* __restrict__ b,
           const float* __restrict__ x, float* __restrict__ y,
           const float* state, const float* t,
           float* out_state, float* cpg_out) {
    constexpr int COLS = 4096;
    int r0 = blockIdx.x * 4;
    {
        const char* wb = (const char*)(W + (size_t)r0 * COLS);
#pragma unroll
        for (int l = 0; l < 2; l++)
            l2_pf_line(wb + ((unsigned)threadIdx.x + l * 256u) * 128u);
    }
    pdl_trigger();
    pdl_sync();

    const float4* W0 = (const float4*)(W + (size_t)r0 * COLS);
    const float4* W1 = (const float4*)(W + (size_t)(r0 + 1) * COLS);
    const float4* W2 = (const float4*)(W + (size_t)(r0 + 2) * COLS);
    const float4* W3 = (const float4*)(W + (size_t)(r0 + 3) * COLS);
    const float4* x4 = (const float4*)x;
    float s0 = 0.0f, s1 = 0.0f, s2 = 0.0f, s3 = 0.0f;
#pragma unroll
    for (int it = 0; it < 4; it++) {
        int j = threadIdx.x + it * 256;
        float4 v  = x4[j];
        float4 w0 = __ldcs(W0 + j);
        float4 w1 = __ldcs(W1 + j);
        float4 w2 = __ldcs(W2 + j);
        float4 w3 = __ldcs(W3 + j);
        s0 += w0.x * v.x + w0.y * v.y + w0.z * v.z + w0.w * v.w;
        s1 += w1.x * v.x + w1.y * v.y + w1.z * v.z + w1.w * v.w;
        s2 += w2.x * v.x + w2.y * v.y + w2.z * v.z + w2.w * v.w;
        s3 += w3.x * v.x + w3.y * v.y + w3.z * v.z + w3.w * v.w;
    }
    __shared__ float sm[4][8];
    int lane = threadIdx.x & 31, w = threadIdx.x >> 5;
    s0 = warp_reduce(s0); s1 = warp_reduce(s1);
    s2 = warp_reduce(s2); s3 = warp_reduce(s3);
    if (lane == 0) { sm[0][w] = s0; sm[1][w] = s1; sm[2][w] = s2; sm[3][w] = s3; }
    __syncthreads();
    if (w == 0) {
        int rr = lane >> 3, sl = lane & 7;
        float v = sm[rr][sl];
        v += __shfl_down_sync(0xffffffffu, v, 4);
        v += __shfl_down_sync(0xffffffffu, v, 2);
        v += __shfl_down_sync(0xffffffffu, v, 1);
        if (sl == 0) y[r0 + rr] = v + b[r0 + rr];  // no relu (params layer)
    }

    // last-block election: one block does the CPG step; nobody waits
    __shared__ unsigned sh_last;
    __threadfence();          // release this block's y writes
    __syncthreads();
    if (threadIdx.x == 0)
        sh_last = (atomicAdd(&g_done, 1u) == gridDim.x - 1u) ? 1u : 0u;
    __syncthreads();
    if (sh_last) {
        if (threadIdx.x == 0) g_done = 0; // reset for next graph replay
        cpg_compute(y, state, t, out_state, cpg_out);
    }
}

// Small GEMV (cols = 64): 2 rows/warp, 4 warps/block (8 rows), 128 threads.
__global__ void __launch_bounds__(128)
gemv_w64(const float* __restrict__ W, const float* __restrict__ b,
         const float* __restrict__ x, float* __restrict__ y) {
    {   // prefetch this block's 8 rows (8*64*4 = 2 KB = 16 lines)
        const char* wb = (const char*)(W + (size_t)blockIdx.x * 8 * 64);
        if (threadIdx.x < 16) l2_pf_line(wb + (unsigned)threadIdx.x * 128u);
    }
    pdl_trigger();
    pdl_sync();

    int warp_id = (blockIdx.x * blockDim.x + threadIdx.x) >> 5;
    int lane = threadIdx.x & 31;
    int r0 = warp_id * 2;
    const float* W0 = W + (size_t)r0 * 64;
    const float* W1 = W0 + 64;
    float x0 = x[lane], x1 = x[32 + lane];
    float s0 = fmaf(W0[lane], x0, W0[32 + lane] * x1);
    float s1 = fmaf(W1[lane], x0, W1[32 + lane] * x1);
    s0 = warp_reduce(s0);
    s1 = warp_reduce(s1);
    if (lane == 0) {
        y[r0]     = fmaxf(s0 + b[r0], 0.0f);
        y[r0 + 1] = fmaxf(s1 + b[r0 + 1], 0.0f);
    }
}

// ---------------- host ----------------
extern "C" void kernel_launch(void* const* d_in, const int* in_sizes, int n_in,
                              void* d_out, int out_size) {
    const float* state = (const float*)d_in[0];
    const float* x     = (const float*)d_in[1];
    const float* t     = (const float*)d_in[2];
    const float* inW0  = (const float*)d_in[3];
    const float* inb0  = (const float*)d_in[4];
    const float* inW1  = (const float*)d_in[5];
    const float* inb1  = (const float*)d_in[6];
    const float* inW2  = (const float*)d_in[7];
    const float* inb2  = (const float*)d_in[8];
    const float* outW0 = (const float*)d_in[9];
    const float* outb0 = (const float*)d_in[10];
    const float* outW1 = (const float*)d_in[11];
    const float* outb1 = (const float*)d_in[12];
    const float* outW2 = (const float*)d_in[13];
    const float* outb2 = (const float*)d_in[14];
    float* out = (float*)d_out;

    float *h1, *h2, *params, *cpg, *h3, *h4;
    cudaGetSymbolAddress((void**)&h1, g_h1);
    cudaGetSymbolAddress((void**)&h2, g_h2);
    cudaGetSymbolAddress((void**)&params, g_params);
    cudaGetSymbolAddress((void**)&cpg, g_cpg);
    cudaGetSymbolAddress((void**)&h3, g_h3);
    cudaGetSymbolAddress((void**)&h4, g_h4);

    // PDL launch config (programmatic stream serialization on every launch)
    cudaLaunchAttribute at[1];
    at[0].id = cudaLaunchAttributeProgrammaticStreamSerialization;
    at[0].val.programmaticStreamSerializationAllowed = 1;
    cudaLaunchConfig_t cfg = {};
    cfg.attrs = at;
    cfg.numAttrs = 1;

    // input MLP; third layer fuses the CPG RK4 step into its last block
    cfg.blockDim = {128, 1, 1};
    cfg.gridDim = {1024, 1, 1};
    cudaLaunchKernelEx(&cfg, gemv_in0, inW0, inb0, x, t, h1);
    cfg.gridDim = {1024, 1, 1};
    cudaLaunchKernelEx(&cfg, gemv4s<4096, true>,
                       inW1, inb1, (const float*)h1, h2);
    cfg.blockDim = {256, 1, 1};
    cfg.gridDim = {528, 1, 1};
    cudaLaunchKernelEx(&cfg, gemv4_fuse,
                       inW2, inb2, (const float*)h2, params, state, t, out, cpg);

    // output MLP
    cfg.blockDim = {128, 1, 1};
    cfg.gridDim = {256, 1, 1};
    cudaLaunchKernelEx(&cfg, gemv_w64, outW0, outb0, (const float*)cpg, h3);
    cfg.gridDim = {512, 1, 1};
    cudaLaunchKernelEx(&cfg, gemv4s<2048, true>,
                       outW1, outb1, (const float*)h3, h4);
    cfg.gridDim = {256, 1, 1};
    cudaLaunchKernelEx(&cfg, gemv4s<2048, false>,
                       outW2, outb2, (const float*)h4, out + 96);
}

// round 17
// speedup vs baseline: 1.0520x; 1.0520x over previous
#include <cuda_runtime.h>
#include <cuda_bf16.h>
#include <math.h>

// ---------------- scratch (no cudaMalloc allowed) ----------------
__device__ __align__(16) float g_h1[4096];     // after in_W0
__device__ __align__(16) float g_h2[4096];     // after in_W1
__device__ __align__(16) float g_params[2112]; // after in_W2
__device__ __align__(16) float g_cpg[64];      // cpg_out
__device__ __align__(16) float g_h3[2048];     // after out_W0
__device__ __align__(16) float g_h4[2048];     // after out_W1
__device__ unsigned g_done = 0;                // last-block counter (self-resetting)

// ---------------- PDL helpers ----------------
__device__ __forceinline__ void pdl_trigger() {
#if defined(__CUDA_ARCH__) && __CUDA_ARCH__ >= 900
    cudaTriggerProgrammaticLaunchCompletion();
#endif
}
__device__ __forceinline__ void pdl_sync() {
#if defined(__CUDA_ARCH__) && __CUDA_ARCH__ >= 900
    cudaGridDependencySynchronize();
#endif
}
__device__ __forceinline__ void l2_pf_line(const char* p) {
    asm volatile("prefetch.global.L2 [%0];" :: "l"(p));
}

// ---------------- reductions ----------------
__device__ __forceinline__ float warp_reduce(float v) {
#pragma unroll
    for (int o = 16; o; o >>= 1) v += __shfl_down_sync(0xffffffffu, v, o);
    return v;
}

// ---------------- accurate sin: fp32 Cody-Waite 3-term + quadrant ----------
// Immune to --use_fast_math (hand-rolled). DP fallback for |x|>32768 (unused
// in practice). qoff=1 gives cos.
__device__ __forceinline__ float trig_acc(float x, int qoff) {
    float q, r;
    if (__builtin_expect(fabsf(x) > 32768.0f, 0)) {
        double xd = (double)x;
        double qd = rint(xd * 0.63661977236758138);
        q = (float)qd;
        r = (float)fma(qd, -1.5707963267948966, xd);
    } else {
        q = rintf(x * 0.63661977236758138f);
        r = fmaf(q, -1.5703125f, x);
        r = fmaf(q, -4.837512969970703125e-4f, r);
        r = fmaf(q, -7.549789948768648e-8f, r);
    }
    int n = ((int)q + qoff) & 3;
    float r2 = r * r;
    float ps = fmaf(r2, fmaf(r2, -1.9515295891e-4f, 8.3321608736e-3f), -1.6666654611e-1f);
    float s  = fmaf(r * r2, ps, r);
    float pc = fmaf(r2, fmaf(r2, -1.388731625493765e-3f, 4.166664568298827e-2f),
                    -4.999999905424326e-1f);
    float c  = fmaf(r2, pc, 1.0f);
    float v  = (n & 1) ? c : s;
    return (n & 2) ? -v : v;
}
__device__ __forceinline__ float sin_acc(float x) { return trig_acc(x, 0); }
__device__ __forceinline__ float cos_acc(float x) { return trig_acc(x, 1); }

// ---------------- CPG RK4(3/8) device function (512 threads) ----------------
// i = tid&31 (oscillator), g = tid>>5 (16 groups x 2 coupling partners).
// Serial sin depth per stage = 2 (vs 4 at 256 threads).
// ODE (reference slot permutation replicated exactly):
//   s0' = s1
//   s1' = ifr[i] + sum_j s0[i]*cw[i][j]*sin(s2[j]-s2[i]-pb[i][j])
//   s2' = 1000*(250*(ia[i]-s0[i]) - s1[i])
// Output: a = new[0:32], ph = new[32:64]; cpg_out = [a*cos(ph), a*sin(ph)]
__device__ void cpg_compute512(const float* params, const float* state,
                               const float* t_ptr, float* out_state, float* cpg_out) {
    const int tid = threadIdx.x;  // 0..511
    const int i   = tid & 31;
    const int g   = tid >> 5;     // 0..15

    __shared__ float sh_ph[2][32];
    __shared__ float sh_part[16][32];

    float cwv[2], pbv[2];
#pragma unroll
    for (int k = 0; k < 2; k++) {
        cwv[k] = __ldcg(params + 64 + 32 * i + 2 * g + k);
        pbv[k] = __ldcg(params + 64 + 1024 + 32 * i + 2 * g + k);
    }
    const float ia  = __ldcg(params + i);
    const float ifr = __ldcg(params + 32 + i);
    const float h   = *t_ptr;
    const float s0 = state[i], s1 = state[32 + i], s2 = state[64 + i];

    int stage = 0;
    auto f = [&](float a0, float a1, float a2, float& d0, float& d1, float& d2) {
        int buf = stage & 1;
        if (g == 0) sh_ph[buf][i] = a2;
        __syncthreads();
        const float* ph = sh_ph[buf] + 2 * g;
        float acc0 = cwv[0] * sin_acc(ph[0] - a2 - pbv[0]);
        float acc1 = cwv[1] * sin_acc(ph[1] - a2 - pbv[1]);
        sh_part[g][i] = acc0 + acc1;
        __syncthreads();
        float c0 = (sh_part[0][i]  + sh_part[1][i])  + (sh_part[2][i]  + sh_part[3][i]);
        float c1 = (sh_part[4][i]  + sh_part[5][i])  + (sh_part[6][i]  + sh_part[7][i]);
        float c2 = (sh_part[8][i]  + sh_part[9][i])  + (sh_part[10][i] + sh_part[11][i]);
        float c3 = (sh_part[12][i] + sh_part[13][i]) + (sh_part[14][i] + sh_part[15][i]);
        float coup = (c0 + c1) + (c2 + c3);
        d1 = fmaf(a0, coup, ifr);
        d0 = a1;
        d2 = 1000.0f * fmaf(250.0f, ia - a0, -a1);
        stage++;
    };

    float k10, k11, k12, k20, k21, k22, k30, k31, k32, k40, k41, k42;
    f(s0, s1, s2, k10, k11, k12);
    f(s0 + h * k10 / 3.0f, s1 + h * k11 / 3.0f, s2 + h * k12 / 3.0f, k20, k21, k22);
    f(s0 + h * (k20 - k10 / 3.0f), s1 + h * (k21 - k11 / 3.0f), s2 + h * (k22 - k12 / 3.0f),
      k30, k31, k32);
    f(s0 + h * (k10 - k20 + k30), s1 + h * (k11 - k21 + k31), s2 + h * (k12 - k22 + k32),
      k40, k41, k42);

    float n0 = s0 + h * 0.125f * (k10 + 3.0f * (k20 + k30) + k40);
    float n1 = s1 + h * 0.125f * (k11 + 3.0f * (k21 + k31) + k41);
    float n2 = s2 + h * 0.125f * (k12 + 3.0f * (k22 + k32) + k42);

    if (g == 0) {
        out_state[i]      = n0;
        out_state[32 + i] = n1;
        out_state[64 + i] = n2;
        // a = n0, ph = n1 (reference reads ph from slot [n:2n])
        cpg_out[i]      = n0 * cos_acc(n1);
        cpg_out[32 + i] = n0 * sin_acc(n1);
    }
}

// ---------------- GEMV kernels (4 rows/block, PDL, 256-thread blocks) ------
// Layer 0: rows=4096, cols=2049. Scalar loads; 4 rows/block.
__global__ void __launch_bounds__(256)
gemv_in0(const float* __restrict__ W, const float* __restrict__ b,
         const float* __restrict__ x, const float* __restrict__ t,
         float* __restrict__ y) {
    int r0 = blockIdx.x * 4;
    {   // prefetch this block's weight slice (4*2049*4 B -> 256 lines)
        const char* wb = (const char*)(W + (size_t)r0 * 2049);
        l2_pf_line(wb + (unsigned)threadIdx.x * 128u);
    }
    pdl_trigger();
    pdl_sync();

    const float* W0 = W + (size_t)r0 * 2049;
    const float* W1 = W0 + 2049;
    const float* W2 = W1 + 2049;
    const float* W3 = W2 + 2049;
    float s0 = 0.0f, s1 = 0.0f, s2 = 0.0f, s3 = 0.0f;
#pragma unroll
    for (int it = 0; it < 8; it++) {
        int j = threadIdx.x + it * 256;
        float xv = x[j];
        s0 = fmaf(__ldcs(W0 + j), xv, s0);
        s1 = fmaf(__ldcs(W1 + j), xv, s1);
        s2 = fmaf(__ldcs(W2 + j), xv, s2);
        s3 = fmaf(__ldcs(W3 + j), xv, s3);
    }
    if (threadIdx.x == 0) {
        float tv = *t;
        s0 = fmaf(__ldcs(W0 + 2048), tv, s0);
        s1 = fmaf(__ldcs(W1 + 2048), tv, s1);
        s2 = fmaf(__ldcs(W2 + 2048), tv, s2);
        s3 = fmaf(__ldcs(W3 + 2048), tv, s3);
    }
    __shared__ float sm[4][8];
    int lane = threadIdx.x & 31, w = threadIdx.x >> 5;
    s0 = warp_reduce(s0); s1 = warp_reduce(s1);
    s2 = warp_reduce(s2); s3 = warp_reduce(s3);
    if (lane == 0) { sm[0][w] = s0; sm[1][w] = s1; sm[2][w] = s2; sm[3][w] = s3; }
    __syncthreads();
    if (w == 0) {
        int rr = lane >> 3, sl = lane & 7;
        float v = sm[rr][sl];
        v += __shfl_down_sync(0xffffffffu, v, 4);
        v += __shfl_down_sync(0xffffffffu, v, 2);
        v += __shfl_down_sync(0xffffffffu, v, 1);
        if (sl == 0) y[r0 + rr] = fmaxf(v + b[r0 + rr], 0.0f);
    }
}

// float4 GEMV, 4 rows per 256-thread block, COLS % 1024 == 0.
template<int COLS, bool RELU>
__global__ void __launch_bounds__(256)
gemv4s(const float* __restrict__ W, const float* __restrict__ b,
       const float* __restrict__ x, float* __restrict__ y) {
    constexpr int N4 = COLS / 4;
    constexpr int ITERS = N4 / 256;
    constexpr int PF_LINES = (COLS * 16) / 128;
    int r0 = blockIdx.x * 4;
    {
        const char* wb = (const char*)(W + (size_t)r0 * COLS);
#pragma unroll
        for (int l = 0; l < PF_LINES / 256; l++)
            l2_pf_line(wb + ((unsigned)threadIdx.x + l * 256u) * 128u);
    }
    pdl_trigger();
    pdl_sync();

    const float4* W0 = (const float4*)(W + (size_t)r0 * COLS);
    const float4* W1 = (const float4*)(W + (size_t)(r0 + 1) * COLS);
    const float4* W2 = (const float4*)(W + (size_t)(r0 + 2) * COLS);
    const float4* W3 = (const float4*)(W + (size_t)(r0 + 3) * COLS);
    const float4* x4 = (const float4*)x;
    float s0 = 0.0f, s1 = 0.0f, s2 = 0.0f, s3 = 0.0f;
#pragma unroll
    for (int it = 0; it < ITERS; it++) {
        int j = threadIdx.x + it * 256;
        float4 v  = x4[j];
        float4 w0 = __ldcs(W0 + j);
        float4 w1 = __ldcs(W1 + j);
        float4 w2 = __ldcs(W2 + j);
        float4 w3 = __ldcs(W3 + j);
        s0 += w0.x * v.x + w0.y * v.y + w0.z * v.z + w0.w * v.w;
        s1 += w1.x * v.x + w1.y * v.y + w1.z * v.z + w1.w * v.w;
        s2 += w2.x * v.x + w2.y * v.y + w2.z * v.z + w2.w * v.w;
        s3 += w3.x * v.x + w3.y * v.y + w3.z * v.z + w3.w * v.w;
    }
    __shared__ float sm[4][8];
    int lane = threadIdx.x & 31, w = threadIdx.x >> 5;
    s0 = warp_reduce(s0); s1 = warp_reduce(s1);
    s2 = warp_reduce(s2); s3 = warp_reduce(s3);
    if (lane == 0) { sm[0][w] = s0; sm[1][w] = s1; sm[2][w] = s2; sm[3][w] = s3; }
    __syncthreads();
    if (w == 0) {
        int rr = lane >> 3, sl = lane & 7;
        float v = sm[rr][sl];
        v += __shfl_down_sync(0xffffffffu, v, 4);
        v += __shfl_down_sync(0xffffffffu, v, 2);
        v += __shfl_down_sync(0xffffffffu, v, 1);
        if (sl == 0) {
            float r = v + b[r0 + rr];
            y[r0 + rr] = RELU ? fmaxf(r, 0.0f) : r;
        }
    }
}

// Fused params layer: 512 threads, 4 rows/block, PDL.
// The last-arriving block runs the CPG step inline (512-thread version).
__global__ void __launch_bounds__(512)
gemv4_fuse(const float* __restrict__ W, const float* __restrict__ b,
           const float* __restrict__ x, float* __restrict__ y,
           const float* state, const float* t,
           float* out_state, float* cpg_out) {
    constexpr int COLS = 4096;
    int r0 = blockIdx.x * 4;
    {   // 4 rows * 4096 * 4B = 512 lines; 1 line/thread
        const char* wb = (const char*)(W + (size_t)r0 * COLS);
        l2_pf_line(wb + (unsigned)threadIdx.x * 128u);
    }
    pdl_trigger();
    pdl_sync();

    const float4* W0 = (const float4*)(W + (size_t)r0 * COLS);
    const float4* W1 = (const float4*)(W + (size_t)(r0 + 1) * COLS);
    const float4* W2 = (const float4*)(W + (size_t)(r0 + 2) * COLS);
    const float4* W3 = (const float4*)(W + (size_t)(r0 + 3) * COLS);
    const float4* x4 = (const float4*)x;
    float s0 = 0.0f, s1 = 0.0f, s2 = 0.0f, s3 = 0.0f;
#pragma unroll
    for (int it = 0; it < 2; it++) {
        int j = threadIdx.x + it * 512;
        float4 v  = x4[j];
        float4 w0 = __ldcs(W0 + j);
        float4 w1 = __ldcs(W1 + j);
        float4 w2 = __ldcs(W2 + j);
        float4 w3 = __ldcs(W3 + j);
        s0 += w0.x * v.x + w0.y * v.y + w0.z * v.z + w0.w * v.w;
        s1 += w1.x * v.x + w1.y * v.y + w1.z * v.z + w1.w * v.w;
        s2 += w2.x * v.x + w2.y * v.y + w2.z * v.z + w2.w * v.w;
        s3 += w3.x * v.x + w3.y * v.y + w3.z * v.z + w3.w * v.w;
    }
    __shared__ float sm[4][16];
    int lane = threadIdx.x & 31, w = threadIdx.x >> 5;
    s0 = warp_reduce(s0); s1 = warp_reduce(s1);
    s2 = warp_reduce(s2); s3 = warp_reduce(s3);
    if (lane == 0) { sm[0][w] = s0; sm[1][w] = s1; sm[2][w] = s2; sm[3][w] = s3; }
    __syncthreads();
    if (threadIdx.x < 64) {
        int rr = threadIdx.x >> 4, sl = threadIdx.x & 15;
        float v = sm[rr][sl];
        v += __shfl_down_sync(0xffffffffu, v, 8);
        v += __shfl_down_sync(0xffffffffu, v, 4);
        v += __shfl_down_sync(0xffffffffu, v, 2);
        v += __shfl_down_sync(0xffffffffu, v, 1);
        if (sl == 0) y[r0 + rr] = v + b[r0 + rr];  // no relu (params layer)
    }

    // last-block election: one block does the CPG step; nobody waits
    __shared__ unsigned sh_last;
    __threadfence();          // release this block's y writes
    __syncthreads();
    if (threadIdx.x == 0)
        sh_last = (atomicAdd(&g_done, 1u) == gridDim.x - 1u) ? 1u : 0u;
    __syncthreads();
    if (sh_last) {
        if (threadIdx.x == 0) g_done = 0; // reset for next graph replay
        cpg_compute512(y, state, t, out_state, cpg_out);
    }
}

// Small GEMV (cols = 64): 2 rows per warp, 8 warps/block (16 rows/block).
__global__ void __launch_bounds__(256)
gemv_w64(const float* __restrict__ W, const float* __restrict__ b,
         const float* __restrict__ x, float* __restrict__ y) {
    {   // prefetch this block's 16 rows (16*64*4 = 4 KB = 32 lines)
        const char* wb = (const char*)(W + (size_t)blockIdx.x * 16 * 64);
        if (threadIdx.x < 32) l2_pf_line(wb + (unsigned)threadIdx.x * 128u);
    }
    pdl_trigger();
    pdl_sync();

    int warp_id = (blockIdx.x * blockDim.x + threadIdx.x) >> 5;
    int lane = threadIdx.x & 31;
    int r0 = warp_id * 2;
    const float* W0 = W + (size_t)r0 * 64;
    const float* W1 = W0 + 64;
    float x0 = x[lane], x1 = x[32 + lane];
    float s0 = fmaf(W0[lane], x0, W0[32 + lane] * x1);
    float s1 = fmaf(W1[lane], x0, W1[32 + lane] * x1);
    s0 = warp_reduce(s0);
    s1 = warp_reduce(s1);
    if (lane == 0) {
        y[r0]     = fmaxf(s0 + b[r0], 0.0f);
        y[r0 + 1] = fmaxf(s1 + b[r0 + 1], 0.0f);
    }
}

// ---------------- host ----------------
extern "C" void kernel_launch(void* const* d_in, const int* in_sizes, int n_in,
                              void* d_out, int out_size) {
    const float* state = (const float*)d_in[0];
    const float* x     = (const float*)d_in[1];
    const float* t     = (const float*)d_in[2];
    const float* inW0  = (const float*)d_in[3];
    const float* inb0  = (const float*)d_in[4];
    const float* inW1  = (const float*)d_in[5];
    const float* inb1  = (const float*)d_in[6];
    const float* inW2  = (const float*)d_in[7];
    const float* inb2  = (const float*)d_in[8];
    const float* outW0 = (const float*)d_in[9];
    const float* outb0 = (const float*)d_in[10];
    const float* outW1 = (const float*)d_in[11];
    const float* outb1 = (const float*)d_in[12];
    const float* outW2 = (const float*)d_in[13];
    const float* outb2 = (const float*)d_in[14];
    float* out = (float*)d_out;

    float *h1, *h2, *params, *cpg, *h3, *h4;
    cudaGetSymbolAddress((void**)&h1, g_h1);
    cudaGetSymbolAddress((void**)&h2, g_h2);
    cudaGetSymbolAddress((void**)&params, g_params);
    cudaGetSymbolAddress((void**)&cpg, g_cpg);
    cudaGetSymbolAddress((void**)&h3, g_h3);
    cudaGetSymbolAddress((void**)&h4, g_h4);

    // PDL launch config (programmatic stream serialization on every launch)
    cudaLaunchAttribute at[1];
    at[0].id = cudaLaunchAttributeProgrammaticStreamSerialization;
    at[0].val.programmaticStreamSerializationAllowed = 1;
    cudaLaunchConfig_t cfg = {};
    cfg.attrs = at;
    cfg.numAttrs = 1;

    // input MLP; third layer fuses the CPG RK4 step into its last block
    cfg.blockDim = {256, 1, 1};
    cfg.gridDim = {1024, 1, 1};
    cudaLaunchKernelEx(&cfg, gemv_in0, inW0, inb0, x, t, h1);
    cfg.gridDim = {1024, 1, 1};
    cudaLaunchKernelEx(&cfg, gemv4s<4096, true>,
                       inW1, inb1, (const float*)h1, h2);
    cfg.blockDim = {512, 1, 1};
    cfg.gridDim = {528, 1, 1};
    cudaLaunchKernelEx(&cfg, gemv4_fuse,
                       inW2, inb2, (const float*)h2, params, state, t, out, cpg);

    // output MLP
    cfg.blockDim = {256, 1, 1};
    cfg.gridDim = {128, 1, 1};
    cudaLaunchKernelEx(&cfg, gemv_w64, outW0, outb0, (const float*)cpg, h3);
    cfg.gridDim = {512, 1, 1};
    cudaLaunchKernelEx(&cfg, gemv4s<2048, true>,
                       outW1, outb1, (const float*)h3, h4);
    cfg.gridDim = {256, 1, 1};
    cudaLaunchKernelEx(&cfg, gemv4s<2048, false>,
                       outW2, outb2, (const float*)h4, out + 96);
}